// round 1
// baseline (speedup 1.0000x reference)
#include <cuda_runtime.h>
#include <cuda_bf16.h>
#include <math.h>

// Problem constants
#define VOCAB 32000
#define D 256
#define NREP 16
#define NL 6
#define DS 16
#define DC 4
#define DI 512
#define DTR 16
#define NH 4
#define HD 64
#define LSEQ 128
#define ROWS (NREP * LSEQ)   // 2048

// ------------------------- scratch buffers (device globals) -------------------------
__device__ float g_h[ROWS * D];          // residual stream, rows = (bn, l)
__device__ float g_xn[ROWS * D];         // LN output (also permuted for attention)
__device__ float g_xz[ROWS * 2 * DI];    // in_proj output
__device__ float g_u[ROWS * DI];         // conv+silu output
__device__ float g_xdbl[ROWS * (DTR + 2 * DS)];
__device__ float g_dt[ROWS * DI];
__device__ float g_y[ROWS * DI];         // scan output -> gated
__device__ float g_qkv[ROWS * 3 * D];
__device__ float g_att[ROWS * D];        // attention output (rows = (l, n))
__device__ float g_co[ROWS * D];         // attn out-proj output (rows = (l, n))
__device__ float g_pool[LSEQ * D];
__device__ float g_pool2[LSEQ * D];

// ------------------------- helpers -------------------------
__device__ __forceinline__ float siluf(float x) {
    return x / (1.f + __expf(-x));
}
__device__ __forceinline__ float softplusf(float x) {
    return (x > 20.f) ? x : log1pf(expf(x));
}

// ------------------------- embed -------------------------
__global__ void embed_kernel(const int* __restrict__ x, const float* __restrict__ emb) {
    int row = blockIdx.x;           // bn*L + l
    int l = row & (LSEQ - 1);
    int tok = x[l];
    g_h[(size_t)row * D + threadIdx.x] = emb[(size_t)tok * D + threadIdx.x];
}

// ------------------------- layernorm (D=256, one block/row) -------------------------
__global__ void ln_kernel(const float* __restrict__ in, const float* __restrict__ w,
                          const float* __restrict__ b, float* __restrict__ out,
                          int permute) {
    int row = blockIdx.x;
    int tid = threadIdx.x;
    __shared__ float sbuf[8];
    float x = in[(size_t)row * D + tid];

    float v = x;
    #pragma unroll
    for (int o = 16; o > 0; o >>= 1) v += __shfl_xor_sync(0xffffffffu, v, o);
    if ((tid & 31) == 0) sbuf[tid >> 5] = v;
    __syncthreads();
    float mean = (sbuf[0]+sbuf[1]+sbuf[2]+sbuf[3]+sbuf[4]+sbuf[5]+sbuf[6]+sbuf[7]) * (1.f / D);
    __syncthreads();

    float d = x - mean;
    float v2 = d * d;
    #pragma unroll
    for (int o = 16; o > 0; o >>= 1) v2 += __shfl_xor_sync(0xffffffffu, v2, o);
    if ((tid & 31) == 0) sbuf[tid >> 5] = v2;
    __syncthreads();
    float var = (sbuf[0]+sbuf[1]+sbuf[2]+sbuf[3]+sbuf[4]+sbuf[5]+sbuf[6]+sbuf[7]) * (1.f / D);

    float r = d * rsqrtf(var + 1e-5f) * w[tid] + b[tid];
    int orow = row;
    if (permute) {  // (bn, l) -> (l, bn)
        int bn = row >> 7, l = row & (LSEQ - 1);
        orow = (l << 4) | bn;
    }
    out[(size_t)orow * D + tid] = r;
}

// ------------------------- generic GEMM: C[M,N] = act(A[M,K] @ W[N,K]^T + bias) + resid
// 128x128 tile, BK=8, 256 threads, 8x8 microtile.
__global__ void gemm_kernel(const float* __restrict__ A, int lda,
                            const float* __restrict__ W,
                            const float* __restrict__ bias,
                            const float* __restrict__ resid,
                            float* __restrict__ C, int ldc,
                            int M, int N, int K, int act) {
    __shared__ float As[8][132];
    __shared__ float Bs[8][132];
    const int bm = blockIdx.y * 128;
    const int bn = blockIdx.x * 128;
    const int tid = threadIdx.x;
    const int tk = tid & 7;
    const int trow = tid >> 3;          // 0..31
    const int tm = (tid >> 4) * 8;      // 0..120
    const int tn = (tid & 15) * 8;

    float acc[8][8];
    #pragma unroll
    for (int i = 0; i < 8; i++)
        #pragma unroll
        for (int j = 0; j < 8; j++) acc[i][j] = 0.f;

    for (int k0 = 0; k0 < K; k0 += 8) {
        #pragma unroll
        for (int i = 0; i < 4; i++) {
            int m = trow + i * 32;
            int gm = bm + m, gk = k0 + tk;
            As[tk][m] = (gm < M && gk < K) ? A[(size_t)gm * lda + gk] : 0.f;
            int gn = bn + m;
            Bs[tk][m] = (gn < N && gk < K) ? W[(size_t)gn * K + gk] : 0.f;
        }
        __syncthreads();
        #pragma unroll
        for (int k = 0; k < 8; k++) {
            float4 a0 = *(const float4*)&As[k][tm];
            float4 a1 = *(const float4*)&As[k][tm + 4];
            float4 b0 = *(const float4*)&Bs[k][tn];
            float4 b1 = *(const float4*)&Bs[k][tn + 4];
            float a[8] = {a0.x, a0.y, a0.z, a0.w, a1.x, a1.y, a1.z, a1.w};
            float b[8] = {b0.x, b0.y, b0.z, b0.w, b1.x, b1.y, b1.z, b1.w};
            #pragma unroll
            for (int i = 0; i < 8; i++)
                #pragma unroll
                for (int j = 0; j < 8; j++) acc[i][j] = fmaf(a[i], b[j], acc[i][j]);
        }
        __syncthreads();
    }

    #pragma unroll
    for (int i = 0; i < 8; i++) {
        int gm = bm + tm + i;
        if (gm >= M) break;
        #pragma unroll
        for (int j = 0; j < 8; j++) {
            int gn = bn + tn + j;
            if (gn >= N) continue;
            float v = acc[i][j];
            if (bias) v += bias[gn];
            if (act == 1) v = softplusf(v);
            if (resid) v += resid[(size_t)gm * ldc + gn];
            C[(size_t)gm * ldc + gn] = v;
        }
    }
}

// ------------------------- depthwise causal conv + silu -------------------------
__global__ void conv_kernel(const float* __restrict__ cw, const float* __restrict__ cb) {
    int bn = blockIdx.x;
    int di = threadIdx.x;  // 512
    float w0 = cw[di * 4 + 0], w1 = cw[di * 4 + 1], w2 = cw[di * 4 + 2], w3 = cw[di * 4 + 3];
    float bb = cb[di];
    float x0 = 0.f, x1 = 0.f, x2 = 0.f;
    const float* base = g_xz + (size_t)bn * LSEQ * (2 * DI) + di;
    float* ob = g_u + (size_t)bn * LSEQ * DI + di;
    for (int l = 0; l < LSEQ; l++) {
        float xc = base[(size_t)l * (2 * DI)];
        float s = w0 * x0 + w1 * x1 + w2 * x2 + w3 * xc + bb;
        ob[(size_t)l * DI] = siluf(s);
        x0 = x1; x1 = x2; x2 = xc;
    }
}

// ------------------------- selective scan: thread per (bn, d), 16 states in regs ----
__global__ void scan_kernel(const float* __restrict__ A_log, const float* __restrict__ dskip) {
    int bn = blockIdx.x >> 3;
    int d = ((blockIdx.x & 7) << 6) + threadIdx.x;   // 64 threads/block
    float Aa[DS];
    #pragma unroll
    for (int s = 0; s < DS; s++) Aa[s] = -__expf(A_log[(size_t)d * DS + s]);
    float skip = dskip[d];
    float hs[DS];
    #pragma unroll
    for (int s = 0; s < DS; s++) hs[s] = 0.f;

    for (int l = 0; l < LSEQ; l++) {
        size_t base = (size_t)(bn * LSEQ + l);
        float dt = g_dt[base * DI + d];
        float uu = g_u[base * DI + d];
        float dtu = dt * uu;
        const float* xr = g_xdbl + base * (DTR + 2 * DS);
        float y = 0.f;
        #pragma unroll
        for (int s = 0; s < DS; s++) {
            float Bv = xr[DTR + s];
            float Cv = xr[DTR + DS + s];
            hs[s] = __expf(dt * Aa[s]) * hs[s] + dtu * Bv;
            y = fmaf(hs[s], Cv, y);
        }
        g_y[base * DI + d] = y + uu * skip;
    }
}

// ------------------------- gate: y *= silu(z) -------------------------
__global__ void gate_kernel() {
    int row = blockIdx.x;
    int d = threadIdx.x;  // 512
    float z = g_xz[(size_t)row * (2 * DI) + DI + d];
    g_y[(size_t)row * DI + d] *= siluf(z);
}

// ------------------------- attention across replicas (S=16, 4 heads of 64) ---------
__global__ void attn_kernel() {
    int l = blockIdx.x;
    __shared__ float sk[16][D];
    __shared__ float sv[16][D];
    int tid = threadIdx.x;  // 256
    for (int i = tid; i < 16 * D; i += 256) {
        int n = i >> 8, d = i & 255;
        size_t r = (size_t)(l * 16 + n) * (3 * D);
        sk[n][d] = g_qkv[r + D + d];
        sv[n][d] = g_qkv[r + 2 * D + d];
    }
    __syncthreads();
    int w = tid >> 5, lane = tid & 31;
    for (int p = w; p < NH * 16; p += 8) {
        int hh = p >> 4, qn = p & 15;
        const float* qp = g_qkv + (size_t)(l * 16 + qn) * (3 * D) + hh * HD;
        float s;
        if (lane < 16) {
            float acc = 0.f;
            for (int d2 = 0; d2 < HD; d2++) acc = fmaf(qp[d2], sk[lane][hh * HD + d2], acc);
            s = acc * 0.125f;  // 1/sqrt(64)
        } else {
            s = -1e30f;
        }
        float mx = s;
        #pragma unroll
        for (int o = 8; o > 0; o >>= 1) mx = fmaxf(mx, __shfl_xor_sync(0xffffffffu, mx, o));
        float e = (lane < 16) ? __expf(s - mx) : 0.f;
        float sum = e;
        #pragma unroll
        for (int o = 8; o > 0; o >>= 1) sum += __shfl_xor_sync(0xffffffffu, sum, o);
        float att = e / sum;
        float o0 = 0.f, o1 = 0.f;
        #pragma unroll
        for (int kn = 0; kn < 16; kn++) {
            float a = __shfl_sync(0xffffffffu, att, kn);
            o0 = fmaf(a, sv[kn][hh * HD + lane], o0);
            o1 = fmaf(a, sv[kn][hh * HD + 32 + lane], o1);
        }
        size_t orow = (size_t)(l * 16 + qn) * D + hh * HD;
        g_att[orow + lane] = o0;
        g_att[orow + 32 + lane] = o1;
    }
}

// ------------------------- permute-add attn output back to residual ----------------
__global__ void permadd_kernel() {
    int row = blockIdx.x;                 // (l, n)
    int l = row >> 4, n = row & 15;
    g_h[(size_t)(n * LSEQ + l) * D + threadIdx.x] += g_co[(size_t)row * D + threadIdx.x];
}

// ------------------------- mean over replicas -------------------------
__global__ void mean_kernel() {
    int l = blockIdx.x;
    int d = threadIdx.x;
    float acc = 0.f;
    #pragma unroll
    for (int n = 0; n < NREP; n++) acc += g_h[(size_t)(n * LSEQ + l) * D + d];
    g_pool[(size_t)l * D + d] = acc * (1.f / NREP);
}

// ------------------------- launch -------------------------
static float* symaddr(const void* sym) {
    void* p = nullptr;
    cudaGetSymbolAddress(&p, sym);
    return (float*)p;
}

extern "C" void kernel_launch(void* const* d_in, const int* in_sizes, int n_in,
                              void* d_out, int out_size) {
    const int*   x    = (const int*)d_in[0];
    const float* emb  = (const float*)d_in[1];
    const float* n1w  = (const float*)d_in[2];
    const float* n1b  = (const float*)d_in[3];
    const float* n2w  = (const float*)d_in[4];
    const float* n2b  = (const float*)d_in[5];
    const float* ipw  = (const float*)d_in[6];
    const float* cw   = (const float*)d_in[7];
    const float* cb   = (const float*)d_in[8];
    const float* xpw  = (const float*)d_in[9];
    const float* dpw  = (const float*)d_in[10];
    const float* dpb  = (const float*)d_in[11];
    const float* alog = (const float*)d_in[12];
    const float* dskp = (const float*)d_in[13];
    const float* opw  = (const float*)d_in[14];
    const float* aiw  = (const float*)d_in[15];
    const float* aib  = (const float*)d_in[16];
    const float* aow  = (const float*)d_in[17];
    const float* aob  = (const float*)d_in[18];
    const float* nfw  = (const float*)d_in[19];
    const float* nfb  = (const float*)d_in[20];
    const float* hb   = (const float*)d_in[21];

    float* b_h    = symaddr(g_h);
    float* b_xn   = symaddr(g_xn);
    float* b_xz   = symaddr(g_xz);
    float* b_u    = symaddr(g_u);
    float* b_xdbl = symaddr(g_xdbl);
    float* b_dt   = symaddr(g_dt);
    float* b_y    = symaddr(g_y);
    float* b_qkv  = symaddr(g_qkv);
    float* b_att  = symaddr(g_att);
    float* b_co   = symaddr(g_co);
    float* b_pool = symaddr(g_pool);
    float* b_pool2= symaddr(g_pool2);

    embed_kernel<<<ROWS, D>>>(x, emb);

    for (int i = 0; i < NL; i++) {
        // ---- Mamba block ----
        ln_kernel<<<ROWS, D>>>(b_h, n1w + i * D, n1b + i * D, b_xn, 0);
        gemm_kernel<<<dim3(8, 16), 256>>>(b_xn, D, ipw + (size_t)i * 2 * DI * D,
                                          nullptr, nullptr, b_xz, 2 * DI,
                                          ROWS, 2 * DI, D, 0);
        conv_kernel<<<NREP, DI>>>(cw + (size_t)i * DI * DC, cb + (size_t)i * DI);
        gemm_kernel<<<dim3(1, 16), 256>>>(b_u, DI, xpw + (size_t)i * (DTR + 2 * DS) * DI,
                                          nullptr, nullptr, b_xdbl, DTR + 2 * DS,
                                          ROWS, DTR + 2 * DS, DI, 0);
        gemm_kernel<<<dim3(4, 16), 256>>>(b_xdbl, DTR + 2 * DS, dpw + (size_t)i * DI * DTR,
                                          dpb + (size_t)i * DI, nullptr, b_dt, DI,
                                          ROWS, DI, DTR, 1);
        scan_kernel<<<128, 64>>>(alog + (size_t)i * DI * DS, dskp + (size_t)i * DI);
        gate_kernel<<<ROWS, DI>>>();
        gemm_kernel<<<dim3(2, 16), 256>>>(b_y, DI, opw + (size_t)i * D * DI,
                                          nullptr, b_h, b_h, D,
                                          ROWS, D, DI, 0);
        // ---- Attention block (across the 16 replicas at each position) ----
        ln_kernel<<<ROWS, D>>>(b_h, n2w + i * D, n2b + i * D, b_xn, 1);
        gemm_kernel<<<dim3(6, 16), 256>>>(b_xn, D, aiw + (size_t)i * 3 * D * D,
                                          aib + (size_t)i * 3 * D, nullptr, b_qkv, 3 * D,
                                          ROWS, 3 * D, D, 0);
        attn_kernel<<<LSEQ, 256>>>();
        gemm_kernel<<<dim3(2, 16), 256>>>(b_att, D, aow + (size_t)i * D * D,
                                          aob + (size_t)i * D, nullptr, b_co, D,
                                          ROWS, D, D, 0);
        permadd_kernel<<<ROWS, D>>>();
    }

    mean_kernel<<<LSEQ, D>>>();
    ln_kernel<<<LSEQ, D>>>(b_pool, nfw, nfb, b_pool2, 0);
    gemm_kernel<<<dim3(VOCAB / 128, 1), 256>>>(b_pool2, D, emb, hb, nullptr,
                                               (float*)d_out, VOCAB,
                                               LSEQ, VOCAB, D, 0);
}

// round 4
// speedup vs baseline: 1.5082x; 1.5082x over previous
#include <cuda_runtime.h>
#include <cuda_bf16.h>
#include <math.h>
#include <stdint.h>

// Problem constants
#define VOCAB 32000
#define D 256
#define NREP 16
#define NL 6
#define DS 16
#define DC 4
#define DI 512
#define DTR 16
#define NH 4
#define HD 64
#define LSEQ 128
#define ROWS (NREP * LSEQ)   // 2048

// ------------------------- scratch buffers (device globals) -------------------------
__device__ float g_h[ROWS * D];          // residual stream, rows = (bn, l)
__device__ float g_xn[ROWS * D];         // LN output (also permuted for attention)
__device__ float g_xz[ROWS * 2 * DI];    // in_proj output
__device__ float g_u[ROWS * DI];         // conv+silu output
__device__ float g_xdbl[ROWS * (DTR + 2 * DS)];
__device__ float g_dt[ROWS * DI];
__device__ float g_y[ROWS * DI];         // scan output (gated)
__device__ float g_qkv[ROWS * 3 * D];
__device__ float g_att[ROWS * D];        // attention output (rows = (l, n))
__device__ float g_pool[LSEQ * D];
__device__ float g_pool2[LSEQ * D];

// ------------------------- helpers -------------------------
__device__ __forceinline__ float siluf(float x) {
    return x / (1.f + __expf(-x));
}
__device__ __forceinline__ float softplusf(float x) {
    return (x > 20.f) ? x : log1pf(expf(x));
}
__device__ __forceinline__ float tf32r(float x) {
    asm("cvt.rna.tf32.f32 %0, %0;" : "+f"(x));
    return x;
}
// 3xTF32 split: x ~= hi + lo, both exactly representable in tf32
__device__ __forceinline__ void tf32split(float x, uint32_t& hi, uint32_t& lo) {
    float h = tf32r(x);
    hi = __float_as_uint(h);
    lo = __float_as_uint(tf32r(x - h));
}

#define MMA_TF32(c, a, b)                                                  \
    asm volatile(                                                          \
        "mma.sync.aligned.m16n8k8.row.col.f32.tf32.tf32.f32 "              \
        "{%0,%1,%2,%3}, {%4,%5,%6,%7}, {%8,%9}, {%0,%1,%2,%3};"            \
        : "+f"(c[0]), "+f"(c[1]), "+f"(c[2]), "+f"(c[3])                   \
        : "r"(a[0]), "r"(a[1]), "r"(a[2]), "r"(a[3]), "r"(b[0]), "r"(b[1]))

// ------------------------- embed -------------------------
__global__ void embed_kernel(const int* __restrict__ x, const float* __restrict__ emb) {
    int row = blockIdx.x;           // bn*L + l
    int l = row & (LSEQ - 1);
    int tok = x[l];
    g_h[(size_t)row * D + threadIdx.x] = emb[(size_t)tok * D + threadIdx.x];
}

// ------------------------- layernorm (D=256, one block/row) -------------------------
__global__ void ln_kernel(const float* __restrict__ in, const float* __restrict__ w,
                          const float* __restrict__ b, float* __restrict__ out,
                          int permute) {
    int row = blockIdx.x;
    int tid = threadIdx.x;
    __shared__ float sbuf[8];
    float x = in[(size_t)row * D + tid];

    float v = x;
    #pragma unroll
    for (int o = 16; o > 0; o >>= 1) v += __shfl_xor_sync(0xffffffffu, v, o);
    if ((tid & 31) == 0) sbuf[tid >> 5] = v;
    __syncthreads();
    float mean = (sbuf[0]+sbuf[1]+sbuf[2]+sbuf[3]+sbuf[4]+sbuf[5]+sbuf[6]+sbuf[7]) * (1.f / D);
    __syncthreads();

    float d = x - mean;
    float v2 = d * d;
    #pragma unroll
    for (int o = 16; o > 0; o >>= 1) v2 += __shfl_xor_sync(0xffffffffu, v2, o);
    if ((tid & 31) == 0) sbuf[tid >> 5] = v2;
    __syncthreads();
    float var = (sbuf[0]+sbuf[1]+sbuf[2]+sbuf[3]+sbuf[4]+sbuf[5]+sbuf[6]+sbuf[7]) * (1.f / D);

    float r = d * rsqrtf(var + 1e-5f) * w[tid] + b[tid];
    int orow = row;
    if (permute) {  // (bn, l) -> (l, bn)
        int bn = row >> 7, l = row & (LSEQ - 1);
        orow = (l << 4) | bn;
    }
    out[(size_t)orow * D + tid] = r;
}

// ------------------------- 3xTF32 tensor-core GEMM -------------------------
// C[M,N] = act(A[M,K] @ W[N,K]^T + bias) (+ resid, optional row permute)
// Requires M % 128 == 0, N % 64 == 0. Tile 128x64, BK=32, 256 threads.
// flags: bit0 = softplus, bit1 = permute out rows (l*16+n) -> (n*128+l)
__global__ void gemm_tc(const float* __restrict__ A, int lda,
                        const float* __restrict__ W,
                        const float* __restrict__ bias,
                        const float* __restrict__ resid,
                        float* __restrict__ C, int ldc,
                        int M, int N, int K, int flags) {
    __shared__ float As[32][136];   // [k][m], raw fp32
    __shared__ float Bs[64][36];    // [n][k], raw fp32
    const int bm = blockIdx.y * 128;
    const int bn = blockIdx.x * 64;
    const int tid = threadIdx.x;
    const int lane = tid & 31;
    const int w = tid >> 5;
    const int wm = (w >> 1) * 32;   // 4 warps over M
    const int wn = (w & 1) * 32;    // 2 warps over N

    float acc[2][4][4];
    #pragma unroll
    for (int i = 0; i < 2; i++)
        #pragma unroll
        for (int j = 0; j < 4; j++)
            #pragma unroll
            for (int e = 0; e < 4; e++) acc[i][j][e] = 0.f;

    const int ar = tid >> 1;            // 0..127
    const int akc = (tid & 1) * 16;
    const int brn = tid >> 2;           // 0..63
    const int bkq = (tid & 3) * 8;

    for (int k0 = 0; k0 < K; k0 += 32) {
        bool full = (k0 + 32 <= K);
        // A -> As[k][m] (transpose on store)
        const float* Ap = A + (size_t)(bm + ar) * lda + k0 + akc;
        if (full) {
            #pragma unroll
            for (int v = 0; v < 4; v++) {
                float4 f = *(const float4*)(Ap + v * 4);
                As[akc + v*4 + 0][ar] = f.x;
                As[akc + v*4 + 1][ar] = f.y;
                As[akc + v*4 + 2][ar] = f.z;
                As[akc + v*4 + 3][ar] = f.w;
            }
        } else {
            #pragma unroll
            for (int j = 0; j < 16; j++) {
                int gk = k0 + akc + j;
                As[akc + j][ar] = (gk < K) ? Ap[j] : 0.f;
            }
        }
        // W -> Bs[n][k]
        const float* Wp = W + (size_t)(bn + brn) * K + k0 + bkq;
        if (full) {
            #pragma unroll
            for (int v = 0; v < 2; v++) {
                float4 f = *(const float4*)(Wp + v * 4);
                Bs[brn][bkq + v*4 + 0] = f.x;
                Bs[brn][bkq + v*4 + 1] = f.y;
                Bs[brn][bkq + v*4 + 2] = f.z;
                Bs[brn][bkq + v*4 + 3] = f.w;
            }
        } else {
            #pragma unroll
            for (int j = 0; j < 8; j++) {
                int gk = k0 + bkq + j;
                Bs[brn][bkq + j] = (gk < K) ? Wp[j] : 0.f;
            }
        }
        __syncthreads();

        #pragma unroll
        for (int kk = 0; kk < 4; kk++) {
            const int ks = kk * 8;
            uint32_t ah[2][4], al[2][4], bh[4][2], bl[4][2];
            #pragma unroll
            for (int tm = 0; tm < 2; tm++) {
                int m = wm + tm * 16 + (lane >> 2);
                tf32split(As[ks + (lane & 3)][m],     ah[tm][0], al[tm][0]);
                tf32split(As[ks + (lane & 3)][m + 8], ah[tm][1], al[tm][1]);
                tf32split(As[ks + (lane & 3) + 4][m],     ah[tm][2], al[tm][2]);
                tf32split(As[ks + (lane & 3) + 4][m + 8], ah[tm][3], al[tm][3]);
            }
            #pragma unroll
            for (int tn = 0; tn < 4; tn++) {
                int n = wn + tn * 8 + (lane >> 2);
                tf32split(Bs[n][ks + (lane & 3)],     bh[tn][0], bl[tn][0]);
                tf32split(Bs[n][ks + (lane & 3) + 4], bh[tn][1], bl[tn][1]);
            }
            #pragma unroll
            for (int tm = 0; tm < 2; tm++)
                #pragma unroll
                for (int tn = 0; tn < 4; tn++) {
                    MMA_TF32(acc[tm][tn], ah[tm], bl[tn]);   // hi*lo
                    MMA_TF32(acc[tm][tn], al[tm], bh[tn]);   // lo*hi
                    MMA_TF32(acc[tm][tn], ah[tm], bh[tn]);   // hi*hi
                }
        }
        __syncthreads();
    }

    // epilogue
    #pragma unroll
    for (int tm = 0; tm < 2; tm++) {
        #pragma unroll
        for (int e2 = 0; e2 < 2; e2++) {            // row half (+8)
            int row = bm + wm + tm * 16 + (lane >> 2) + e2 * 8;
            int orow = row;
            if (flags & 2) orow = (row & 15) * LSEQ + (row >> 4);
            #pragma unroll
            for (int tn = 0; tn < 4; tn++) {
                #pragma unroll
                for (int e1 = 0; e1 < 2; e1++) {    // col pair
                    int col = bn + wn + tn * 8 + 2 * (lane & 3) + e1;
                    float v = acc[tm][tn][e2 * 2 + e1];
                    if (bias) v += bias[col];
                    if (flags & 1) v = softplusf(v);
                    if (resid) v += resid[(size_t)orow * ldc + col];
                    C[(size_t)orow * ldc + col] = v;
                }
            }
        }
    }
}

// ------------------------- FMA GEMM (kept for x_proj: N=48) -------------------------
__global__ void gemm_kernel(const float* __restrict__ A, int lda,
                            const float* __restrict__ W,
                            float* __restrict__ C, int ldc,
                            int M, int N, int K) {
    __shared__ float As[8][132];
    __shared__ float Bs[8][132];
    const int bm = blockIdx.y * 128;
    const int bn = blockIdx.x * 128;
    const int tid = threadIdx.x;
    const int tk = tid & 7;
    const int trow = tid >> 3;
    const int tm = (tid >> 4) * 8;
    const int tn = (tid & 15) * 8;

    float acc[8][8];
    #pragma unroll
    for (int i = 0; i < 8; i++)
        #pragma unroll
        for (int j = 0; j < 8; j++) acc[i][j] = 0.f;

    for (int k0 = 0; k0 < K; k0 += 8) {
        #pragma unroll
        for (int i = 0; i < 4; i++) {
            int m = trow + i * 32;
            int gm = bm + m, gk = k0 + tk;
            As[tk][m] = (gm < M && gk < K) ? A[(size_t)gm * lda + gk] : 0.f;
            int gn = bn + m;
            Bs[tk][m] = (gn < N && gk < K) ? W[(size_t)gn * K + gk] : 0.f;
        }
        __syncthreads();
        #pragma unroll
        for (int k = 0; k < 8; k++) {
            float4 a0 = *(const float4*)&As[k][tm];
            float4 a1 = *(const float4*)&As[k][tm + 4];
            float4 b0 = *(const float4*)&Bs[k][tn];
            float4 b1 = *(const float4*)&Bs[k][tn + 4];
            float a[8] = {a0.x, a0.y, a0.z, a0.w, a1.x, a1.y, a1.z, a1.w};
            float b[8] = {b0.x, b0.y, b0.z, b0.w, b1.x, b1.y, b1.z, b1.w};
            #pragma unroll
            for (int i = 0; i < 8; i++)
                #pragma unroll
                for (int j = 0; j < 8; j++) acc[i][j] = fmaf(a[i], b[j], acc[i][j]);
        }
        __syncthreads();
    }

    #pragma unroll
    for (int i = 0; i < 8; i++) {
        int gm = bm + tm + i;
        if (gm >= M) break;
        #pragma unroll
        for (int j = 0; j < 8; j++) {
            int gn = bn + tn + j;
            if (gn >= N) continue;
            C[(size_t)gm * ldc + gn] = acc[i][j];
        }
    }
}

// ------------------------- depthwise causal conv + silu (fully parallel) ------------
__global__ void conv_kernel(const float* __restrict__ cw, const float* __restrict__ cb) {
    int idx = blockIdx.x * 256 + threadIdx.x;  // over ROWS*DI
    if (idx >= ROWS * DI) return;
    int di = idx & (DI - 1);
    int row = idx >> 9;
    int l = row & (LSEQ - 1);
    float s = cb[di];
    #pragma unroll
    for (int j = 0; j < DC; j++) {
        int ll = l - (DC - 1) + j;
        if (ll >= 0)
            s = fmaf(cw[di * DC + j], g_xz[(size_t)(row - (DC - 1) + j) * (2 * DI) + di], s);
    }
    g_u[(size_t)row * DI + di] = siluf(s);
}

// ------------------------- selective scan: 4 threads per (bn,d), gate fused --------
__global__ void scan_kernel(const float* __restrict__ A_log, const float* __restrict__ dskip) {
    int t = blockIdx.x * 256 + threadIdx.x;   // 32768 threads
    int pair = t >> 2;                         // (bn, d), 0..8191
    int q = t & 3;                             // state quad
    int bn = pair >> 9;
    int d = pair & (DI - 1);
    float Aa[4];
    #pragma unroll
    for (int j = 0; j < 4; j++) Aa[j] = -expf(A_log[(size_t)d * DS + q * 4 + j]);
    float skip = dskip[d];
    float hs[4] = {0.f, 0.f, 0.f, 0.f};

    for (int l = 0; l < LSEQ; l++) {
        size_t row = (size_t)(bn * LSEQ + l);
        float dt = g_dt[row * DI + d];
        float uu = g_u[row * DI + d];
        float dtu = dt * uu;
        const float* xr = g_xdbl + row * (DTR + 2 * DS);
        float y = 0.f;
        #pragma unroll
        for (int j = 0; j < 4; j++) {
            float Bv = xr[DTR + q * 4 + j];
            float Cv = xr[DTR + DS + q * 4 + j];
            hs[j] = __expf(dt * Aa[j]) * hs[j] + dtu * Bv;
            y = fmaf(hs[j], Cv, y);
        }
        y += __shfl_xor_sync(0xffffffffu, y, 1);
        y += __shfl_xor_sync(0xffffffffu, y, 2);
        if (q == 0) {
            float z = g_xz[row * (2 * DI) + DI + d];
            g_y[row * DI + d] = (y + uu * skip) * siluf(z);
        }
    }
}

// ------------------------- attention across replicas (S=16, 4 heads of 64) ---------
__global__ void attn_kernel() {
    int l = blockIdx.x;
    __shared__ float sk[16][D];
    __shared__ float sv[16][D];
    int tid = threadIdx.x;  // 256
    for (int i = tid; i < 16 * D; i += 256) {
        int n = i >> 8, d = i & 255;
        size_t r = (size_t)(l * 16 + n) * (3 * D);
        sk[n][d] = g_qkv[r + D + d];
        sv[n][d] = g_qkv[r + 2 * D + d];
    }
    __syncthreads();
    int w = tid >> 5, lane = tid & 31;
    for (int p = w; p < NH * 16; p += 8) {
        int hh = p >> 4, qn = p & 15;
        const float* qp = g_qkv + (size_t)(l * 16 + qn) * (3 * D) + hh * HD;
        float s;
        if (lane < 16) {
            float acc = 0.f;
            for (int d2 = 0; d2 < HD; d2++) acc = fmaf(qp[d2], sk[lane][hh * HD + d2], acc);
            s = acc * 0.125f;
        } else {
            s = -1e30f;
        }
        float mx = s;
        #pragma unroll
        for (int o = 8; o > 0; o >>= 1) mx = fmaxf(mx, __shfl_xor_sync(0xffffffffu, mx, o));
        float e = (lane < 16) ? __expf(s - mx) : 0.f;
        float sum = e;
        #pragma unroll
        for (int o = 8; o > 0; o >>= 1) sum += __shfl_xor_sync(0xffffffffu, sum, o);
        float att = e / sum;
        float o0 = 0.f, o1 = 0.f;
        #pragma unroll
        for (int kn = 0; kn < 16; kn++) {
            float a = __shfl_sync(0xffffffffu, att, kn);
            o0 = fmaf(a, sv[kn][hh * HD + lane], o0);
            o1 = fmaf(a, sv[kn][hh * HD + 32 + lane], o1);
        }
        size_t orow = (size_t)(l * 16 + qn) * D + hh * HD;
        g_att[orow + lane] = o0;
        g_att[orow + 32 + lane] = o1;
    }
}

// ------------------------- mean over replicas -------------------------
__global__ void mean_kernel() {
    int l = blockIdx.x;
    int d = threadIdx.x;
    float acc = 0.f;
    #pragma unroll
    for (int n = 0; n < NREP; n++) acc += g_h[(size_t)(n * LSEQ + l) * D + d];
    g_pool[(size_t)l * D + d] = acc * (1.f / NREP);
}

// ------------------------- launch -------------------------
static float* symaddr(const void* sym) {
    void* p = nullptr;
    cudaGetSymbolAddress(&p, sym);
    return (float*)p;
}

extern "C" void kernel_launch(void* const* d_in, const int* in_sizes, int n_in,
                              void* d_out, int out_size) {
    const int*   x    = (const int*)d_in[0];
    const float* emb  = (const float*)d_in[1];
    const float* n1w  = (const float*)d_in[2];
    const float* n1b  = (const float*)d_in[3];
    const float* n2w  = (const float*)d_in[4];
    const float* n2b  = (const float*)d_in[5];
    const float* ipw  = (const float*)d_in[6];
    const float* cw   = (const float*)d_in[7];
    const float* cb   = (const float*)d_in[8];
    const float* xpw  = (const float*)d_in[9];
    const float* dpw  = (const float*)d_in[10];
    const float* dpb  = (const float*)d_in[11];
    const float* alog = (const float*)d_in[12];
    const float* dskp = (const float*)d_in[13];
    const float* opw  = (const float*)d_in[14];
    const float* aiw  = (const float*)d_in[15];
    const float* aib  = (const float*)d_in[16];
    const float* aow  = (const float*)d_in[17];
    const float* aob  = (const float*)d_in[18];
    const float* nfw  = (const float*)d_in[19];
    const float* nfb  = (const float*)d_in[20];
    const float* hb   = (const float*)d_in[21];

    float* b_h    = symaddr(g_h);
    float* b_xn   = symaddr(g_xn);
    float* b_xz   = symaddr(g_xz);
    float* b_u    = symaddr(g_u);
    float* b_xdbl = symaddr(g_xdbl);
    float* b_dt   = symaddr(g_dt);
    float* b_y    = symaddr(g_y);
    float* b_qkv  = symaddr(g_qkv);
    float* b_att  = symaddr(g_att);
    float* b_pool = symaddr(g_pool);
    float* b_pool2= symaddr(g_pool2);

    embed_kernel<<<ROWS, D>>>(x, emb);

    for (int i = 0; i < NL; i++) {
        // ---- Mamba block ----
        ln_kernel<<<ROWS, D>>>(b_h, n1w + i * D, n1b + i * D, b_xn, 0);
        gemm_tc<<<dim3(16, 16), 256>>>(b_xn, D, ipw + (size_t)i * 2 * DI * D,
                                       nullptr, nullptr, b_xz, 2 * DI,
                                       ROWS, 2 * DI, D, 0);
        conv_kernel<<<(ROWS * DI) / 256, 256>>>(cw + (size_t)i * DI * DC, cb + (size_t)i * DI);
        gemm_kernel<<<dim3(1, 16), 256>>>(b_u, DI, xpw + (size_t)i * (DTR + 2 * DS) * DI,
                                          b_xdbl, DTR + 2 * DS,
                                          ROWS, DTR + 2 * DS, DI);
        gemm_tc<<<dim3(8, 16), 256>>>(b_xdbl, DTR + 2 * DS, dpw + (size_t)i * DI * DTR,
                                      dpb + (size_t)i * DI, nullptr, b_dt, DI,
                                      ROWS, DI, DTR, 1);
        scan_kernel<<<128, 256>>>(alog + (size_t)i * DI * DS, dskp + (size_t)i * DI);
        gemm_tc<<<dim3(4, 16), 256>>>(b_y, DI, opw + (size_t)i * D * DI,
                                      nullptr, b_h, b_h, D,
                                      ROWS, D, DI, 0);
        // ---- Attention block (across the 16 replicas at each position) ----
        ln_kernel<<<ROWS, D>>>(b_h, n2w + i * D, n2b + i * D, b_xn, 1);
        gemm_tc<<<dim3(12, 16), 256>>>(b_xn, D, aiw + (size_t)i * 3 * D * D,
                                       aib + (size_t)i * 3 * D, nullptr, b_qkv, 3 * D,
                                       ROWS, 3 * D, D, 0);
        attn_kernel<<<LSEQ, 256>>>();
        gemm_tc<<<dim3(4, 16), 256>>>(b_att, D, aow + (size_t)i * D * D,
                                      aob + (size_t)i * D, b_h, b_h, D,
                                      ROWS, D, D, 2);
    }

    mean_kernel<<<LSEQ, D>>>();
    ln_kernel<<<LSEQ, D>>>(b_pool, nfw, nfb, b_pool2, 0);
    gemm_tc<<<dim3(VOCAB / 64, 1), 256>>>(b_pool2, D, emb, hb, nullptr,
                                          (float*)d_out, VOCAB,
                                          LSEQ, VOCAB, D, 0);
}

// round 6
// speedup vs baseline: 1.7813x; 1.1810x over previous
#include <cuda_runtime.h>
#include <cuda_bf16.h>
#include <math.h>
#include <stdint.h>

// Problem constants
#define VOCAB 32000
#define D 256
#define NREP 16
#define NL 6
#define DS 16
#define DC 4
#define DI 512
#define DTR 16
#define NH 4
#define HD 64
#define LSEQ 128
#define ROWS (NREP * LSEQ)   // 2048
#define XDBL_W (DTR + 2 * DS)   // 48

// ------------------------- scratch buffers (device globals) -------------------------
__device__ float g_h[ROWS * D];
__device__ float g_xn[ROWS * D];
__device__ float g_xz[ROWS * 2 * DI];
__device__ float g_u[ROWS * DI];
__device__ float g_xdbl[ROWS * XDBL_W];
__device__ float g_dt[ROWS * DI];
__device__ float g_y[ROWS * DI];
__device__ float g_qkv[ROWS * 3 * D];
__device__ float g_att[ROWS * D];
__device__ float g_pool[LSEQ * D];
__device__ float g_pool2[LSEQ * D];

// ------------------------- helpers -------------------------
__device__ __forceinline__ float siluf(float x) {
    return x / (1.f + __expf(-x));
}
__device__ __forceinline__ float softplusf(float x) {
    return (x > 20.f) ? x : log1pf(expf(x));
}
__device__ __forceinline__ float tf32r(float x) {
    asm("cvt.rna.tf32.f32 %0, %0;" : "+f"(x));
    return x;
}
__device__ __forceinline__ float2 tf32split2(float x) {
    float h = tf32r(x);
    return make_float2(h, tf32r(x - h));
}

#define MMA_TF32(c, a, b)                                                  \
    asm volatile(                                                          \
        "mma.sync.aligned.m16n8k8.row.col.f32.tf32.tf32.f32 "              \
        "{%0,%1,%2,%3}, {%4,%5,%6,%7}, {%8,%9}, {%0,%1,%2,%3};"            \
        : "+f"(c[0]), "+f"(c[1]), "+f"(c[2]), "+f"(c[3])                   \
        : "r"(a[0]), "r"(a[1]), "r"(a[2]), "r"(a[3]), "r"(b[0]), "r"(b[1]))

// ------------------------- embed -------------------------
__global__ void embed_kernel(const int* __restrict__ x, const float* __restrict__ emb) {
    int row = blockIdx.x;
    int l = row & (LSEQ - 1);
    int tok = x[l];
    g_h[(size_t)row * D + threadIdx.x] = emb[(size_t)tok * D + threadIdx.x];
}

// ------------------------- layernorm (D=256, one block/row) -------------------------
__global__ void ln_kernel(const float* __restrict__ in, const float* __restrict__ w,
                          const float* __restrict__ b, float* __restrict__ out,
                          int permute) {
    int row = blockIdx.x;
    int tid = threadIdx.x;
    __shared__ float sbuf[8];
    float x = in[(size_t)row * D + tid];

    float v = x;
    #pragma unroll
    for (int o = 16; o > 0; o >>= 1) v += __shfl_xor_sync(0xffffffffu, v, o);
    if ((tid & 31) == 0) sbuf[tid >> 5] = v;
    __syncthreads();
    float mean = (sbuf[0]+sbuf[1]+sbuf[2]+sbuf[3]+sbuf[4]+sbuf[5]+sbuf[6]+sbuf[7]) * (1.f / D);
    __syncthreads();

    float d = x - mean;
    float v2 = d * d;
    #pragma unroll
    for (int o = 16; o > 0; o >>= 1) v2 += __shfl_xor_sync(0xffffffffu, v2, o);
    if ((tid & 31) == 0) sbuf[tid >> 5] = v2;
    __syncthreads();
    float var = (sbuf[0]+sbuf[1]+sbuf[2]+sbuf[3]+sbuf[4]+sbuf[5]+sbuf[6]+sbuf[7]) * (1.f / D);

    float r = d * rsqrtf(var + 1e-5f) * w[tid] + b[tid];
    int orow = row;
    if (permute) {  // (bn, l) -> (l, bn)
        int bn = row >> 7, l = row & (LSEQ - 1);
        orow = (l << 4) | bn;
    }
    out[(size_t)orow * D + tid] = r;
}

// ------------------------- 3xTF32 tensor-core GEMM v2 -------------------------
// C[M,N] = act(A[M,K] @ W[N,K]^T + bias) (+ resid, optional row permute)
// Tile 128x64, BK=32, 256 threads. M % 128 == 0, K % 16 == 0; any N (guarded).
// smem holds pre-split (hi,lo) pairs; inner loop = LDS.64 + MMA only.
// flags: bit0 = softplus, bit1 = permute out rows (l*16+n) -> (n*128+l)
#define GEMM_SMEM_BYTES ((32 * 136 + 64 * 40) * 8)
__global__ void gemm_tc(const float* __restrict__ A, int lda,
                        const float* __restrict__ W,
                        const float* __restrict__ bias,
                        const float* __restrict__ resid,
                        float* __restrict__ C, int ldc,
                        int M, int N, int K, int flags) {
    extern __shared__ float2 smemBuf[];
    float2 (*As)[136] = (float2(*)[136])smemBuf;            // [k][m]
    float2 (*Bs)[40]  = (float2(*)[40])(smemBuf + 32 * 136); // [n][k]

    const int bm = blockIdx.y * 128;
    const int bn = blockIdx.x * 64;
    const int tid = threadIdx.x;
    const int lane = tid & 31;
    const int w = tid >> 5;
    const int wm = (w >> 1) * 32;   // 4 warps over M
    const int wn = (w & 1) * 32;    // 2 warps over N
    const int kq = lane & 3;
    const int lrow = lane >> 2;

    float acc[2][4][4];
    #pragma unroll
    for (int i = 0; i < 2; i++)
        #pragma unroll
        for (int j = 0; j < 4; j++)
            #pragma unroll
            for (int e = 0; e < 4; e++) acc[i][j][e] = 0.f;

    const int ar = tid >> 1;            // 0..127
    const int akc = (tid & 1) * 16;
    const int brn = tid >> 2;           // 0..63
    const int bkq = (tid & 3) * 8;
    const bool bOK = (bn + brn) < N;

    float4 ar4[4];
    float4 br4[2];

    // prefetch k0 = 0
    {
        const float* Ap = A + (size_t)(bm + ar) * lda + akc;
        if (akc < K) {
            #pragma unroll
            for (int v = 0; v < 4; v++) ar4[v] = *(const float4*)(Ap + v * 4);
        } else {
            #pragma unroll
            for (int v = 0; v < 4; v++) ar4[v] = make_float4(0.f, 0.f, 0.f, 0.f);
        }
        const float* Wp = W + (size_t)(bn + brn) * K + bkq;
        if (bOK && bkq < K) {
            #pragma unroll
            for (int v = 0; v < 2; v++) br4[v] = *(const float4*)(Wp + v * 4);
        } else {
            #pragma unroll
            for (int v = 0; v < 2; v++) br4[v] = make_float4(0.f, 0.f, 0.f, 0.f);
        }
    }

    const int nk = (K + 31) / 32;
    for (int it = 0; it < nk; it++) {
        // split + store current regs to smem
        {
            const float* af = (const float*)ar4;
            #pragma unroll
            for (int j = 0; j < 16; j++)
                As[akc + j][ar] = tf32split2(af[j]);
            const float* bf2 = (const float*)br4;
            #pragma unroll
            for (int j = 0; j < 8; j++)
                Bs[brn][bkq + j] = tf32split2(bf2[j]);
        }
        __syncthreads();

        // prefetch next tile (overlaps with MMA below)
        if (it + 1 < nk) {
            int k0 = (it + 1) * 32;
            const float* Ap = A + (size_t)(bm + ar) * lda + k0 + akc;
            if (k0 + akc < K) {
                #pragma unroll
                for (int v = 0; v < 4; v++) ar4[v] = *(const float4*)(Ap + v * 4);
            } else {
                #pragma unroll
                for (int v = 0; v < 4; v++) ar4[v] = make_float4(0.f, 0.f, 0.f, 0.f);
            }
            const float* Wp = W + (size_t)(bn + brn) * K + k0 + bkq;
            if (bOK && k0 + bkq < K) {
                #pragma unroll
                for (int v = 0; v < 2; v++) br4[v] = *(const float4*)(Wp + v * 4);
            } else {
                #pragma unroll
                for (int v = 0; v < 2; v++) br4[v] = make_float4(0.f, 0.f, 0.f, 0.f);
            }
        }

        #pragma unroll
        for (int kk = 0; kk < 4; kk++) {
            const int ks = kk * 8;
            float2 a2[2][4], b2[4][2];
            #pragma unroll
            for (int tm = 0; tm < 2; tm++) {
                int m = wm + tm * 16 + lrow;
                a2[tm][0] = As[ks + kq][m];
                a2[tm][1] = As[ks + kq][m + 8];
                a2[tm][2] = As[ks + kq + 4][m];
                a2[tm][3] = As[ks + kq + 4][m + 8];
            }
            #pragma unroll
            for (int tn = 0; tn < 4; tn++) {
                int n = wn + tn * 8 + lrow;
                b2[tn][0] = Bs[n][ks + kq];
                b2[tn][1] = Bs[n][ks + kq + 4];
            }
            uint32_t ah[2][4], al[2][4], bh[4][2], bl[4][2];
            #pragma unroll
            for (int tm = 0; tm < 2; tm++)
                #pragma unroll
                for (int e = 0; e < 4; e++) {
                    ah[tm][e] = __float_as_uint(a2[tm][e].x);
                    al[tm][e] = __float_as_uint(a2[tm][e].y);
                }
            #pragma unroll
            for (int tn = 0; tn < 4; tn++)
                #pragma unroll
                for (int e = 0; e < 2; e++) {
                    bh[tn][e] = __float_as_uint(b2[tn][e].x);
                    bl[tn][e] = __float_as_uint(b2[tn][e].y);
                }
            #pragma unroll
            for (int tm = 0; tm < 2; tm++)
                #pragma unroll
                for (int tn = 0; tn < 4; tn++) {
                    MMA_TF32(acc[tm][tn], ah[tm], bl[tn]);   // hi*lo
                    MMA_TF32(acc[tm][tn], al[tm], bh[tn]);   // lo*hi
                    MMA_TF32(acc[tm][tn], ah[tm], bh[tn]);   // hi*hi
                }
        }
        __syncthreads();
    }

    // epilogue
    #pragma unroll
    for (int tm = 0; tm < 2; tm++) {
        #pragma unroll
        for (int e2 = 0; e2 < 2; e2++) {
            int row = bm + wm + tm * 16 + lrow + e2 * 8;
            int orow = row;
            if (flags & 2) orow = (row & 15) * LSEQ + (row >> 4);
            #pragma unroll
            for (int tn = 0; tn < 4; tn++) {
                #pragma unroll
                for (int e1 = 0; e1 < 2; e1++) {
                    int col = bn + wn + tn * 8 + 2 * (lane & 3) + e1;
                    if (col >= N) continue;
                    float v = acc[tm][tn][e2 * 2 + e1];
                    if (bias) v += bias[col];
                    if (flags & 1) v = softplusf(v);
                    if (resid) v += resid[(size_t)orow * ldc + col];
                    C[(size_t)orow * ldc + col] = v;
                }
            }
        }
    }
}

// ------------------------- depthwise causal conv + silu (fully parallel) ------------
__global__ void conv_kernel(const float* __restrict__ cw, const float* __restrict__ cb) {
    int idx = blockIdx.x * 256 + threadIdx.x;
    if (idx >= ROWS * DI) return;
    int di = idx & (DI - 1);
    int row = idx >> 9;
    int l = row & (LSEQ - 1);
    float s = cb[di];
    #pragma unroll
    for (int j = 0; j < DC; j++) {
        int ll = l - (DC - 1) + j;
        if (ll >= 0)
            s = fmaf(cw[di * DC + j], g_xz[(size_t)(row - (DC - 1) + j) * (2 * DI) + di], s);
    }
    g_u[(size_t)row * DI + di] = siluf(s);
}

// ------------- selective scan: 4 threads per (bn,d), gate fused, pipelined ---------
__global__ void scan_kernel(const float* __restrict__ A_log, const float* __restrict__ dskip) {
    int t = blockIdx.x * 256 + threadIdx.x;   // 32768 threads
    int pair = t >> 2;                         // (bn, d)
    int q = t & 3;                             // state quad
    int bn = pair >> 9;
    int d = pair & (DI - 1);
    float Aa[4];
    #pragma unroll
    for (int j = 0; j < 4; j++) Aa[j] = -expf(A_log[(size_t)d * DS + q * 4 + j]);
    float skip = dskip[d];
    float hs[4] = {0.f, 0.f, 0.f, 0.f};

    const size_t r0 = (size_t)bn * LSEQ;
    // prefetch step 0
    float dt = g_dt[r0 * DI + d];
    float uu = g_u[r0 * DI + d];
    float4 Bv = *(const float4*)(g_xdbl + r0 * XDBL_W + DTR + q * 4);
    float4 Cv = *(const float4*)(g_xdbl + r0 * XDBL_W + DTR + DS + q * 4);
    float z  = g_xz[r0 * (2 * DI) + DI + d];

    for (int l = 0; l < LSEQ; l++) {
        float dt_c = dt, uu_c = uu, z_c = z;
        float4 B_c = Bv, C_c = Cv;
        if (l + 1 < LSEQ) {   // prefetch next step (hides gmem latency behind exp chain)
            size_t r = r0 + l + 1;
            dt = g_dt[r * DI + d];
            uu = g_u[r * DI + d];
            Bv = *(const float4*)(g_xdbl + r * XDBL_W + DTR + q * 4);
            Cv = *(const float4*)(g_xdbl + r * XDBL_W + DTR + DS + q * 4);
            z  = g_xz[r * (2 * DI) + DI + d];
        }
        float dtu = dt_c * uu_c;
        float y;
        hs[0] = __expf(dt_c * Aa[0]) * hs[0] + dtu * B_c.x;  y  = hs[0] * C_c.x;
        hs[1] = __expf(dt_c * Aa[1]) * hs[1] + dtu * B_c.y;  y  = fmaf(hs[1], C_c.y, y);
        hs[2] = __expf(dt_c * Aa[2]) * hs[2] + dtu * B_c.z;  y  = fmaf(hs[2], C_c.z, y);
        hs[3] = __expf(dt_c * Aa[3]) * hs[3] + dtu * B_c.w;  y  = fmaf(hs[3], C_c.w, y);
        y += __shfl_xor_sync(0xffffffffu, y, 1);
        y += __shfl_xor_sync(0xffffffffu, y, 2);
        if (q == 0)
            g_y[(r0 + l) * DI + d] = (y + uu_c * skip) * siluf(z_c);
    }
}

// ------------------------- attention across replicas (S=16, 4 heads of 64) ---------
__global__ void attn_kernel() {
    int l = blockIdx.x;
    __shared__ float sk[16][D];
    __shared__ float sv[16][D];
    int tid = threadIdx.x;  // 256
    for (int i = tid; i < 16 * D; i += 256) {
        int n = i >> 8, d = i & 255;
        size_t r = (size_t)(l * 16 + n) * (3 * D);
        sk[n][d] = g_qkv[r + D + d];
        sv[n][d] = g_qkv[r + 2 * D + d];
    }
    __syncthreads();
    int w = tid >> 5, lane = tid & 31;
    for (int p = w; p < NH * 16; p += 8) {
        int hh = p >> 4, qn = p & 15;
        const float* qp = g_qkv + (size_t)(l * 16 + qn) * (3 * D) + hh * HD;
        float s;
        if (lane < 16) {
            float acc = 0.f;
            for (int d2 = 0; d2 < HD; d2++) acc = fmaf(qp[d2], sk[lane][hh * HD + d2], acc);
            s = acc * 0.125f;
        } else {
            s = -1e30f;
        }
        float mx = s;
        #pragma unroll
        for (int o = 8; o > 0; o >>= 1) mx = fmaxf(mx, __shfl_xor_sync(0xffffffffu, mx, o));
        float e = (lane < 16) ? __expf(s - mx) : 0.f;
        float sum = e;
        #pragma unroll
        for (int o = 8; o > 0; o >>= 1) sum += __shfl_xor_sync(0xffffffffu, sum, o);
        float att = e / sum;
        float o0 = 0.f, o1 = 0.f;
        #pragma unroll
        for (int kn = 0; kn < 16; kn++) {
            float a = __shfl_sync(0xffffffffu, att, kn);
            o0 = fmaf(a, sv[kn][hh * HD + lane], o0);
            o1 = fmaf(a, sv[kn][hh * HD + 32 + lane], o1);
        }
        size_t orow = (size_t)(l * 16 + qn) * D + hh * HD;
        g_att[orow + lane] = o0;
        g_att[orow + 32 + lane] = o1;
    }
}

// ------------------------- mean over replicas -------------------------
__global__ void mean_kernel() {
    int l = blockIdx.x;
    int d = threadIdx.x;
    float acc = 0.f;
    #pragma unroll
    for (int n = 0; n < NREP; n++) acc += g_h[(size_t)(n * LSEQ + l) * D + d];
    g_pool[(size_t)l * D + d] = acc * (1.f / NREP);
}

// ------------------------- launch -------------------------
static float* symaddr(const void* sym) {
    void* p = nullptr;
    cudaGetSymbolAddress(&p, sym);
    return (float*)p;
}

extern "C" void kernel_launch(void* const* d_in, const int* in_sizes, int n_in,
                              void* d_out, int out_size) {
    const int*   x    = (const int*)d_in[0];
    const float* emb  = (const float*)d_in[1];
    const float* n1w  = (const float*)d_in[2];
    const float* n1b  = (const float*)d_in[3];
    const float* n2w  = (const float*)d_in[4];
    const float* n2b  = (const float*)d_in[5];
    const float* ipw  = (const float*)d_in[6];
    const float* cw   = (const float*)d_in[7];
    const float* cb   = (const float*)d_in[8];
    const float* xpw  = (const float*)d_in[9];
    const float* dpw  = (const float*)d_in[10];
    const float* dpb  = (const float*)d_in[11];
    const float* alog = (const float*)d_in[12];
    const float* dskp = (const float*)d_in[13];
    const float* opw  = (const float*)d_in[14];
    const float* aiw  = (const float*)d_in[15];
    const float* aib  = (const float*)d_in[16];
    const float* aow  = (const float*)d_in[17];
    const float* aob  = (const float*)d_in[18];
    const float* nfw  = (const float*)d_in[19];
    const float* nfb  = (const float*)d_in[20];
    const float* hb   = (const float*)d_in[21];

    float* b_h    = symaddr(g_h);
    float* b_xn   = symaddr(g_xn);
    float* b_xz   = symaddr(g_xz);
    float* b_u    = symaddr(g_u);
    float* b_xdbl = symaddr(g_xdbl);
    float* b_dt   = symaddr(g_dt);
    float* b_y    = symaddr(g_y);
    float* b_qkv  = symaddr(g_qkv);
    float* b_att  = symaddr(g_att);
    float* b_pool = symaddr(g_pool);
    float* b_pool2= symaddr(g_pool2);

    static int smemSet = 0;
    if (!smemSet) {
        cudaFuncSetAttribute(gemm_tc, cudaFuncAttributeMaxDynamicSharedMemorySize,
                             GEMM_SMEM_BYTES);
        smemSet = 1;
    }
    const int SB = GEMM_SMEM_BYTES;

    embed_kernel<<<ROWS, D>>>(x, emb);

    for (int i = 0; i < NL; i++) {
        // ---- Mamba block ----
        ln_kernel<<<ROWS, D>>>(b_h, n1w + i * D, n1b + i * D, b_xn, 0);
        gemm_tc<<<dim3(16, 16), 256, SB>>>(b_xn, D, ipw + (size_t)i * 2 * DI * D,
                                           nullptr, nullptr, b_xz, 2 * DI,
                                           ROWS, 2 * DI, D, 0);
        conv_kernel<<<(ROWS * DI) / 256, 256>>>(cw + (size_t)i * DI * DC, cb + (size_t)i * DI);
        gemm_tc<<<dim3(1, 16), 256, SB>>>(b_u, DI, xpw + (size_t)i * XDBL_W * DI,
                                          nullptr, nullptr, b_xdbl, XDBL_W,
                                          ROWS, XDBL_W, DI, 0);
        gemm_tc<<<dim3(8, 16), 256, SB>>>(b_xdbl, XDBL_W, dpw + (size_t)i * DI * DTR,
                                          dpb + (size_t)i * DI, nullptr, b_dt, DI,
                                          ROWS, DI, DTR, 1);
        scan_kernel<<<128, 256>>>(alog + (size_t)i * DI * DS, dskp + (size_t)i * DI);
        gemm_tc<<<dim3(4, 16), 256, SB>>>(b_y, DI, opw + (size_t)i * D * DI,
                                          nullptr, b_h, b_h, D,
                                          ROWS, D, DI, 0);
        // ---- Attention block ----
        ln_kernel<<<ROWS, D>>>(b_h, n2w + i * D, n2b + i * D, b_xn, 1);
        gemm_tc<<<dim3(12, 16), 256, SB>>>(b_xn, D, aiw + (size_t)i * 3 * D * D,
                                           aib + (size_t)i * 3 * D, nullptr, b_qkv, 3 * D,
                                           ROWS, 3 * D, D, 0);
        attn_kernel<<<LSEQ, 256>>>();
        gemm_tc<<<dim3(4, 16), 256, SB>>>(b_att, D, aow + (size_t)i * D * D,
                                          aob + (size_t)i * D, b_h, b_h, D,
                                          ROWS, D, D, 2);
    }

    mean_kernel<<<LSEQ, D>>>();
    ln_kernel<<<LSEQ, D>>>(b_pool, nfw, nfb, b_pool2, 0);
    gemm_tc<<<dim3(VOCAB / 64, 1), 256, SB>>>(b_pool2, D, emb, hb, nullptr,
                                              (float*)d_out, VOCAB,
                                              LSEQ, VOCAB, D, 0);
}

// round 7
// speedup vs baseline: 2.5548x; 1.4343x over previous
#include <cuda_runtime.h>
#include <cuda_bf16.h>
#include <math.h>
#include <stdint.h>

// Problem constants
#define VOCAB 32000
#define D 256
#define NREP 16
#define NL 6
#define DS 16
#define DC 4
#define DI 512
#define DTR 16
#define NH 4
#define HD 64
#define LSEQ 128
#define ROWS (NREP * LSEQ)   // 2048
#define XDBL_W (DTR + 2 * DS)   // 48

// ------------------------- scratch buffers (device globals) -------------------------
__device__ float g_h[ROWS * D];
__device__ float g_xn[ROWS * D];
__device__ float g_xz[ROWS * 2 * DI];
__device__ float g_u[ROWS * DI];
__device__ float g_xdbl[ROWS * XDBL_W];
__device__ float g_dt[ROWS * DI];
__device__ float g_y[ROWS * DI];
__device__ float g_qkv[ROWS * 3 * D];
__device__ float g_att[ROWS * D];
__device__ float g_pool[LSEQ * D];
__device__ float g_pool2[LSEQ * D];

// ------------------------- helpers -------------------------
__device__ __forceinline__ float siluf(float x) {
    return x / (1.f + __expf(-x));
}
__device__ __forceinline__ float softplusf(float x) {
    return (x > 20.f) ? x : log1pf(expf(x));
}
// pack two floats into bf16x2: lo element = first k, hi element = second k
__device__ __forceinline__ uint32_t bf16pack(float klo, float khi) {
    uint32_t r;
    asm("cvt.rn.bf16x2.f32 %0, %1, %2;" : "=r"(r) : "f"(khi), "f"(klo));
    return r;
}
__device__ __forceinline__ float bf16lo_f(uint32_t p)  { return __uint_as_float(p << 16); }
__device__ __forceinline__ float bf16hi_f(uint32_t p)  { return __uint_as_float(p & 0xffff0000u); }
// split two consecutive fp32 into packed (hi-part pair, lo-part pair)
__device__ __forceinline__ void bf16split2(float x0, float x1, uint32_t& hp, uint32_t& lp) {
    hp = bf16pack(x0, x1);
    lp = bf16pack(x0 - bf16lo_f(hp), x1 - bf16hi_f(hp));
}

#define MMA_BF16(c, a, b)                                                  \
    asm volatile(                                                          \
        "mma.sync.aligned.m16n8k16.row.col.f32.bf16.bf16.f32 "             \
        "{%0,%1,%2,%3}, {%4,%5,%6,%7}, {%8,%9}, {%0,%1,%2,%3};"            \
        : "+f"(c[0]), "+f"(c[1]), "+f"(c[2]), "+f"(c[3])                   \
        : "r"(a[0]), "r"(a[1]), "r"(a[2]), "r"(a[3]), "r"(b[0]), "r"(b[1]))

// ------------------------- embed -------------------------
__global__ void embed_kernel(const int* __restrict__ x, const float* __restrict__ emb) {
    int row = blockIdx.x;
    int l = row & (LSEQ - 1);
    int tok = x[l];
    g_h[(size_t)row * D + threadIdx.x] = emb[(size_t)tok * D + threadIdx.x];
}

// ------------------------- layernorm (D=256, one block/row) -------------------------
__global__ void ln_kernel(const float* __restrict__ in, const float* __restrict__ w,
                          const float* __restrict__ b, float* __restrict__ out,
                          int permute) {
    int row = blockIdx.x;
    int tid = threadIdx.x;
    __shared__ float sbuf[8];
    float x = in[(size_t)row * D + tid];

    float v = x;
    #pragma unroll
    for (int o = 16; o > 0; o >>= 1) v += __shfl_xor_sync(0xffffffffu, v, o);
    if ((tid & 31) == 0) sbuf[tid >> 5] = v;
    __syncthreads();
    float mean = (sbuf[0]+sbuf[1]+sbuf[2]+sbuf[3]+sbuf[4]+sbuf[5]+sbuf[6]+sbuf[7]) * (1.f / D);
    __syncthreads();

    float d = x - mean;
    float v2 = d * d;
    #pragma unroll
    for (int o = 16; o > 0; o >>= 1) v2 += __shfl_xor_sync(0xffffffffu, v2, o);
    if ((tid & 31) == 0) sbuf[tid >> 5] = v2;
    __syncthreads();
    float var = (sbuf[0]+sbuf[1]+sbuf[2]+sbuf[3]+sbuf[4]+sbuf[5]+sbuf[6]+sbuf[7]) * (1.f / D);

    float r = d * rsqrtf(var + 1e-5f) * w[tid] + b[tid];
    int orow = row;
    if (permute) {  // (bn, l) -> (l, bn)
        int bn = row >> 7, l = row & (LSEQ - 1);
        orow = (l << 4) | bn;
    }
    out[(size_t)orow * D + tid] = r;
}

// ------------------------- 3x-split bf16 tensor-core GEMM -------------------------
// C[M,N] = act(A[M,K] @ W[N,K]^T + bias) (+ resid, optional row permute)
// Tile 128x64, BK=32, 256 threads. M % 128 == 0; any N (guarded); K padded w/ zeros.
// smem holds bf16x2 (pair along k) hi-plane and lo-plane; frag load = 1 LDS.32.
// Error-compensated: acc += Ahi*Blo + Alo*Bhi + Ahi*Bhi  (per-product err ~2^-17)
// flags: bit0 = softplus, bit1 = permute out rows (l*16+n) -> (n*128+l)
__global__ void __launch_bounds__(256) gemm_tc(
                        const float* __restrict__ A, int lda,
                        const float* __restrict__ W,
                        const float* __restrict__ bias,
                        const float* __restrict__ resid,
                        float* __restrict__ C, int ldc,
                        int M, int N, int K, int flags) {
    __shared__ uint32_t Ahi[16][136];  // [kpair][m]
    __shared__ uint32_t Alo[16][136];
    __shared__ uint32_t Bhi[64][20];   // [n][kpair]
    __shared__ uint32_t Blo[64][20];

    const int bm = blockIdx.y * 128;
    const int bn = blockIdx.x * 64;
    const int tid = threadIdx.x;
    const int lane = tid & 31;
    const int w = tid >> 5;
    const int wm = (w >> 1) * 32;   // 4 warps over M
    const int wn = (w & 1) * 32;    // 2 warps over N
    const int kq = lane & 3;
    const int lrow = lane >> 2;

    float acc[2][4][4];
    #pragma unroll
    for (int i = 0; i < 2; i++)
        #pragma unroll
        for (int j = 0; j < 4; j++)
            #pragma unroll
            for (int e = 0; e < 4; e++) acc[i][j][e] = 0.f;

    const int ar  = tid >> 1;           // 0..127  (A row within tile)
    const int akc = (tid & 1) * 16;     // A k offset (16 floats)
    const int akp = (tid & 1) * 8;      // A kpair offset
    const int brn = tid >> 2;           // 0..63   (B row = n)
    const int bkc = (tid & 3) * 8;      // B k offset (8 floats)
    const int bkp = (tid & 3) * 4;      // B kpair offset
    const bool bOK = (bn + brn) < N;

    float4 ar4[4];
    float4 br4[2];

    // prefetch k0 = 0
    {
        const float* Ap = A + (size_t)(bm + ar) * lda + akc;
        if (akc < K) {
            #pragma unroll
            for (int v = 0; v < 4; v++) ar4[v] = *(const float4*)(Ap + v * 4);
        } else {
            #pragma unroll
            for (int v = 0; v < 4; v++) ar4[v] = make_float4(0.f, 0.f, 0.f, 0.f);
        }
        const float* Wp = W + (size_t)(bn + brn) * K + bkc;
        if (bOK && bkc < K) {
            #pragma unroll
            for (int v = 0; v < 2; v++) br4[v] = *(const float4*)(Wp + v * 4);
        } else {
            #pragma unroll
            for (int v = 0; v < 2; v++) br4[v] = make_float4(0.f, 0.f, 0.f, 0.f);
        }
    }

    const int nk = (K + 31) / 32;
    for (int it = 0; it < nk; it++) {
        // split + store current regs to smem (hi/lo planes, bf16x2 pairs along k)
        {
            const float* af = (const float*)ar4;
            #pragma unroll
            for (int j = 0; j < 8; j++) {
                uint32_t hp, lp;
                bf16split2(af[2*j], af[2*j+1], hp, lp);
                Ahi[akp + j][ar] = hp;
                Alo[akp + j][ar] = lp;
            }
            const float* bf2 = (const float*)br4;
            #pragma unroll
            for (int j = 0; j < 4; j++) {
                uint32_t hp, lp;
                bf16split2(bf2[2*j], bf2[2*j+1], hp, lp);
                Bhi[brn][bkp + j] = hp;
                Blo[brn][bkp + j] = lp;
            }
        }
        __syncthreads();

        // prefetch next tile (overlaps with MMA below)
        if (it + 1 < nk) {
            int k0 = (it + 1) * 32;
            const float* Ap = A + (size_t)(bm + ar) * lda + k0 + akc;
            if (k0 + akc < K) {
                #pragma unroll
                for (int v = 0; v < 4; v++) ar4[v] = *(const float4*)(Ap + v * 4);
            } else {
                #pragma unroll
                for (int v = 0; v < 4; v++) ar4[v] = make_float4(0.f, 0.f, 0.f, 0.f);
            }
            const float* Wp = W + (size_t)(bn + brn) * K + k0 + bkc;
            if (bOK && k0 + bkc < K) {
                #pragma unroll
                for (int v = 0; v < 2; v++) br4[v] = *(const float4*)(Wp + v * 4);
            } else {
                #pragma unroll
                for (int v = 0; v < 2; v++) br4[v] = make_float4(0.f, 0.f, 0.f, 0.f);
            }
        }

        // two k16 chunks per BK=32
        #pragma unroll
        for (int kk = 0; kk < 2; kk++) {
            const int kb = kk * 8;   // kpair base
            uint32_t ah[2][4], al[2][4], bh[4][2], bl[4][2];
            #pragma unroll
            for (int tm = 0; tm < 2; tm++) {
                int m = wm + tm * 16 + lrow;
                ah[tm][0] = Ahi[kb + kq][m];      al[tm][0] = Alo[kb + kq][m];
                ah[tm][1] = Ahi[kb + kq][m + 8];  al[tm][1] = Alo[kb + kq][m + 8];
                ah[tm][2] = Ahi[kb + kq + 4][m];      al[tm][2] = Alo[kb + kq + 4][m];
                ah[tm][3] = Ahi[kb + kq + 4][m + 8];  al[tm][3] = Alo[kb + kq + 4][m + 8];
            }
            #pragma unroll
            for (int tn = 0; tn < 4; tn++) {
                int n = wn + tn * 8 + lrow;
                bh[tn][0] = Bhi[n][kb + kq];      bl[tn][0] = Blo[n][kb + kq];
                bh[tn][1] = Bhi[n][kb + kq + 4];  bl[tn][1] = Blo[n][kb + kq + 4];
            }
            #pragma unroll
            for (int tm = 0; tm < 2; tm++)
                #pragma unroll
                for (int tn = 0; tn < 4; tn++) {
                    MMA_BF16(acc[tm][tn], ah[tm], bl[tn]);   // hi*lo
                    MMA_BF16(acc[tm][tn], al[tm], bh[tn]);   // lo*hi
                    MMA_BF16(acc[tm][tn], ah[tm], bh[tn]);   // hi*hi
                }
        }
        __syncthreads();
    }

    // epilogue
    #pragma unroll
    for (int tm = 0; tm < 2; tm++) {
        #pragma unroll
        for (int e2 = 0; e2 < 2; e2++) {
            int row = bm + wm + tm * 16 + lrow + e2 * 8;
            int orow = row;
            if (flags & 2) orow = (row & 15) * LSEQ + (row >> 4);
            #pragma unroll
            for (int tn = 0; tn < 4; tn++) {
                #pragma unroll
                for (int e1 = 0; e1 < 2; e1++) {
                    int col = bn + wn + tn * 8 + 2 * (lane & 3) + e1;
                    if (col >= N) continue;
                    float v = acc[tm][tn][e2 * 2 + e1];
                    if (bias) v += bias[col];
                    if (flags & 1) v = softplusf(v);
                    if (resid) v += resid[(size_t)orow * ldc + col];
                    C[(size_t)orow * ldc + col] = v;
                }
            }
        }
    }
}

// ------------------------- depthwise causal conv + silu (fully parallel) ------------
__global__ void conv_kernel(const float* __restrict__ cw, const float* __restrict__ cb) {
    int idx = blockIdx.x * 256 + threadIdx.x;
    if (idx >= ROWS * DI) return;
    int di = idx & (DI - 1);
    int row = idx >> 9;
    int l = row & (LSEQ - 1);
    float s = cb[di];
    #pragma unroll
    for (int j = 0; j < DC; j++) {
        int ll = l - (DC - 1) + j;
        if (ll >= 0)
            s = fmaf(cw[di * DC + j], g_xz[(size_t)(row - (DC - 1) + j) * (2 * DI) + di], s);
    }
    g_u[(size_t)row * DI + di] = siluf(s);
}

// ------------- selective scan: 4 threads per (bn,d), gate fused, pipelined ---------
__global__ void scan_kernel(const float* __restrict__ A_log, const float* __restrict__ dskip) {
    int t = blockIdx.x * 256 + threadIdx.x;   // 32768 threads
    int pair = t >> 2;                         // (bn, d)
    int q = t & 3;                             // state quad
    int bn = pair >> 9;
    int d = pair & (DI - 1);
    float Aa[4];
    #pragma unroll
    for (int j = 0; j < 4; j++) Aa[j] = -expf(A_log[(size_t)d * DS + q * 4 + j]);
    float skip = dskip[d];
    float hs[4] = {0.f, 0.f, 0.f, 0.f};

    const size_t r0 = (size_t)bn * LSEQ;
    float dt = g_dt[r0 * DI + d];
    float uu = g_u[r0 * DI + d];
    float4 Bv = *(const float4*)(g_xdbl + r0 * XDBL_W + DTR + q * 4);
    float4 Cv = *(const float4*)(g_xdbl + r0 * XDBL_W + DTR + DS + q * 4);
    float z  = g_xz[r0 * (2 * DI) + DI + d];

    for (int l = 0; l < LSEQ; l++) {
        float dt_c = dt, uu_c = uu, z_c = z;
        float4 B_c = Bv, C_c = Cv;
        if (l + 1 < LSEQ) {
            size_t r = r0 + l + 1;
            dt = g_dt[r * DI + d];
            uu = g_u[r * DI + d];
            Bv = *(const float4*)(g_xdbl + r * XDBL_W + DTR + q * 4);
            Cv = *(const float4*)(g_xdbl + r * XDBL_W + DTR + DS + q * 4);
            z  = g_xz[r * (2 * DI) + DI + d];
        }
        float dtu = dt_c * uu_c;
        float y;
        hs[0] = __expf(dt_c * Aa[0]) * hs[0] + dtu * B_c.x;  y  = hs[0] * C_c.x;
        hs[1] = __expf(dt_c * Aa[1]) * hs[1] + dtu * B_c.y;  y  = fmaf(hs[1], C_c.y, y);
        hs[2] = __expf(dt_c * Aa[2]) * hs[2] + dtu * B_c.z;  y  = fmaf(hs[2], C_c.z, y);
        hs[3] = __expf(dt_c * Aa[3]) * hs[3] + dtu * B_c.w;  y  = fmaf(hs[3], C_c.w, y);
        y += __shfl_xor_sync(0xffffffffu, y, 1);
        y += __shfl_xor_sync(0xffffffffu, y, 2);
        if (q == 0)
            g_y[(r0 + l) * DI + d] = (y + uu_c * skip) * siluf(z_c);
    }
}

// ------------------------- attention across replicas (S=16, 4 heads of 64) ---------
__global__ void attn_kernel() {
    int l = blockIdx.x;
    __shared__ float sk[16][D];
    __shared__ float sv[16][D];
    int tid = threadIdx.x;  // 256
    for (int i = tid; i < 16 * D; i += 256) {
        int n = i >> 8, d = i & 255;
        size_t r = (size_t)(l * 16 + n) * (3 * D);
        sk[n][d] = g_qkv[r + D + d];
        sv[n][d] = g_qkv[r + 2 * D + d];
    }
    __syncthreads();
    int w = tid >> 5, lane = tid & 31;
    for (int p = w; p < NH * 16; p += 8) {
        int hh = p >> 4, qn = p & 15;
        const float* qp = g_qkv + (size_t)(l * 16 + qn) * (3 * D) + hh * HD;
        float s;
        if (lane < 16) {
            float acc = 0.f;
            for (int d2 = 0; d2 < HD; d2++) acc = fmaf(qp[d2], sk[lane][hh * HD + d2], acc);
            s = acc * 0.125f;
        } else {
            s = -1e30f;
        }
        float mx = s;
        #pragma unroll
        for (int o = 8; o > 0; o >>= 1) mx = fmaxf(mx, __shfl_xor_sync(0xffffffffu, mx, o));
        float e = (lane < 16) ? __expf(s - mx) : 0.f;
        float sum = e;
        #pragma unroll
        for (int o = 8; o > 0; o >>= 1) sum += __shfl_xor_sync(0xffffffffu, sum, o);
        float att = e / sum;
        float o0 = 0.f, o1 = 0.f;
        #pragma unroll
        for (int kn = 0; kn < 16; kn++) {
            float a = __shfl_sync(0xffffffffu, att, kn);
            o0 = fmaf(a, sv[kn][hh * HD + lane], o0);
            o1 = fmaf(a, sv[kn][hh * HD + 32 + lane], o1);
        }
        size_t orow = (size_t)(l * 16 + qn) * D + hh * HD;
        g_att[orow + lane] = o0;
        g_att[orow + 32 + lane] = o1;
    }
}

// ------------------------- mean over replicas -------------------------
__global__ void mean_kernel() {
    int l = blockIdx.x;
    int d = threadIdx.x;
    float acc = 0.f;
    #pragma unroll
    for (int n = 0; n < NREP; n++) acc += g_h[(size_t)(n * LSEQ + l) * D + d];
    g_pool[(size_t)l * D + d] = acc * (1.f / NREP);
}

// ------------------------- launch -------------------------
static float* symaddr(const void* sym) {
    void* p = nullptr;
    cudaGetSymbolAddress(&p, sym);
    return (float*)p;
}

extern "C" void kernel_launch(void* const* d_in, const int* in_sizes, int n_in,
                              void* d_out, int out_size) {
    const int*   x    = (const int*)d_in[0];
    const float* emb  = (const float*)d_in[1];
    const float* n1w  = (const float*)d_in[2];
    const float* n1b  = (const float*)d_in[3];
    const float* n2w  = (const float*)d_in[4];
    const float* n2b  = (const float*)d_in[5];
    const float* ipw  = (const float*)d_in[6];
    const float* cw   = (const float*)d_in[7];
    const float* cb   = (const float*)d_in[8];
    const float* xpw  = (const float*)d_in[9];
    const float* dpw  = (const float*)d_in[10];
    const float* dpb  = (const float*)d_in[11];
    const float* alog = (const float*)d_in[12];
    const float* dskp = (const float*)d_in[13];
    const float* opw  = (const float*)d_in[14];
    const float* aiw  = (const float*)d_in[15];
    const float* aib  = (const float*)d_in[16];
    const float* aow  = (const float*)d_in[17];
    const float* aob  = (const float*)d_in[18];
    const float* nfw  = (const float*)d_in[19];
    const float* nfb  = (const float*)d_in[20];
    const float* hb   = (const float*)d_in[21];

    float* b_h    = symaddr(g_h);
    float* b_xn   = symaddr(g_xn);
    float* b_xz   = symaddr(g_xz);
    float* b_u    = symaddr(g_u);
    float* b_xdbl = symaddr(g_xdbl);
    float* b_dt   = symaddr(g_dt);
    float* b_y    = symaddr(g_y);
    float* b_qkv  = symaddr(g_qkv);
    float* b_att  = symaddr(g_att);
    float* b_pool = symaddr(g_pool);
    float* b_pool2= symaddr(g_pool2);

    embed_kernel<<<ROWS, D>>>(x, emb);

    for (int i = 0; i < NL; i++) {
        // ---- Mamba block ----
        ln_kernel<<<ROWS, D>>>(b_h, n1w + i * D, n1b + i * D, b_xn, 0);
        gemm_tc<<<dim3(16, 16), 256>>>(b_xn, D, ipw + (size_t)i * 2 * DI * D,
                                       nullptr, nullptr, b_xz, 2 * DI,
                                       ROWS, 2 * DI, D, 0);
        conv_kernel<<<(ROWS * DI) / 256, 256>>>(cw + (size_t)i * DI * DC, cb + (size_t)i * DI);
        gemm_tc<<<dim3(1, 16), 256>>>(b_u, DI, xpw + (size_t)i * XDBL_W * DI,
                                      nullptr, nullptr, b_xdbl, XDBL_W,
                                      ROWS, XDBL_W, DI, 0);
        gemm_tc<<<dim3(8, 16), 256>>>(b_xdbl, XDBL_W, dpw + (size_t)i * DI * DTR,
                                      dpb + (size_t)i * DI, nullptr, b_dt, DI,
                                      ROWS, DI, DTR, 1);
        scan_kernel<<<128, 256>>>(alog + (size_t)i * DI * DS, dskp + (size_t)i * DI);
        gemm_tc<<<dim3(4, 16), 256>>>(b_y, DI, opw + (size_t)i * D * DI,
                                      nullptr, b_h, b_h, D,
                                      ROWS, D, DI, 0);
        // ---- Attention block ----
        ln_kernel<<<ROWS, D>>>(b_h, n2w + i * D, n2b + i * D, b_xn, 1);
        gemm_tc<<<dim3(12, 16), 256>>>(b_xn, D, aiw + (size_t)i * 3 * D * D,
                                       aib + (size_t)i * 3 * D, nullptr, b_qkv, 3 * D,
                                       ROWS, 3 * D, D, 0);
        attn_kernel<<<LSEQ, 256>>>();
        gemm_tc<<<dim3(4, 16), 256>>>(b_att, D, aow + (size_t)i * D * D,
                                      aob + (size_t)i * D, b_h, b_h, D,
                                      ROWS, D, D, 2);
    }

    mean_kernel<<<LSEQ, D>>>();
    ln_kernel<<<LSEQ, D>>>(b_pool, nfw, nfb, b_pool2, 0);
    gemm_tc<<<dim3(VOCAB / 64, 1), 256>>>(b_pool2, D, emb, hb, nullptr,
                                          (float*)d_out, VOCAB,
                                          LSEQ, VOCAB, D, 0);
}